// round 1
// baseline (speedup 1.0000x reference)
#include <cuda_runtime.h>
#include <cuda_fp16.h>
#include <cstdint>
#include <math.h>

#define NB 4
#define NS 2048
#define NHID 4096
#define NH 32
#define ND 128
#define NTOK (NB*NS)
#define MLPDIM (3*NHID)

// ---------------- scratch (static device allocations; no cudaMalloc) ----------------
__device__ __half  d_X16 [(size_t)NTOK*NHID];
__device__ __half  d_Wk16[(size_t)NHID*NHID];
__device__ __half  d_Wv16[(size_t)NHID*NHID];
__device__ __half  d_K16 [(size_t)NTOK*NHID];
__device__ __half  d_V16 [(size_t)NTOK*NHID];
__device__ float2  d_cs  [NS*64];
__device__ float   d_scores[NB*NH*NS];
__device__ float   d_attn  [NB*NH*NS];
__device__ float   d_attnv_part[8][NB*NH*ND];
__device__ float   d_attn_out[NB*NHID];
__device__ float   d_y1 [NB*NHID];
__device__ float   d_ln1[NB*NHID];
__device__ float   d_cbuf[NB*MLPDIM];
__device__ float   d_y2 [NB*NHID];
__device__ float   d_ln2[NB*NHID];

// ---------------- helpers ----------------
__device__ __forceinline__ float warp_sum_all(float v) {
    #pragma unroll
    for (int o = 16; o > 0; o >>= 1) v += __shfl_xor_sync(0xffffffffu, v, o);
    return v;
}
__device__ __forceinline__ float warp_max_all(float v) {
    #pragma unroll
    for (int o = 16; o > 0; o >>= 1) v = fmaxf(v, __shfl_xor_sync(0xffffffffu, v, o));
    return v;
}
__device__ __forceinline__ uint32_t smem_u32(const void* p) {
    return (uint32_t)__cvta_generic_to_shared(p);
}

// ---------------- fp32 -> fp16 conversion (X, Wk, Wv in one grid) ----------------
__global__ void __launch_bounds__(256) cvt_all(const float* __restrict__ X,
                                               const float* __restrict__ Wk,
                                               const float* __restrict__ Wv) {
    int i = blockIdx.x * 256 + threadIdx.x;   // each handles 4 floats
    const float* src; __half* dst; int j;
    if (i < 8388608)        { src = X;  dst = d_X16;  j = i; }
    else if (i < 12582912)  { src = Wk; dst = d_Wk16; j = i - 8388608; }
    else                    { src = Wv; dst = d_Wv16; j = i - 12582912; }
    float4 v = *(const float4*)(src + (size_t)j * 4);
    __half2* o = (__half2*)(dst + (size_t)j * 4);
    o[0] = __floats2half2_rn(v.x, v.y);
    o[1] = __floats2half2_rn(v.z, v.w);
}

// ---------------- RoPE cos/sin table: d_cs[s*64 + j] ----------------
__global__ void __launch_bounds__(256) cs_kernel() {
    int i = blockIdx.x * 256 + threadIdx.x;   // s*64 + j
    if (i >= NS * 64) return;
    int s = i >> 6, j = i & 63;
    float theta = powf(10000.f, -2.f * (float)j / 128.f);
    float sv, cv;
    sincosf((float)s * theta, &sv, &cv);
    d_cs[i] = make_float2(cv, sv);
}

// ---------------- GEMM: C[8192,4096] = X16 * W^T (mma.sync m16n8k16 fp16) ----------------
// WHICH=0: W=Wk16 -> K16 (no rope). WHICH=1: W=Wv16 -> V16 (rope in epilogue).
template<int WHICH>
__global__ void __launch_bounds__(256) gemm_kernel() {
    const __half* __restrict__ A  = d_X16;
    const __half* __restrict__ Bw = WHICH ? d_Wv16 : d_Wk16;
    __half* __restrict__ C        = WHICH ? d_V16  : d_K16;

    const int LDS = 72;                       // 64 + 8 pad halves (conflict-free ldmatrix)
    __shared__ __half As[128 * LDS];
    __shared__ __half Bs[128 * LDS];

    int tid  = threadIdx.x;
    int lane = tid & 31, warp = tid >> 5;
    int wm = warp >> 2, wn = warp & 3;        // 2 x 4 warp grid, warp tile 64x32
    int bm = blockIdx.y * 128, bn = blockIdx.x * 128;

    float acc[4][4][4];
    #pragma unroll
    for (int a = 0; a < 4; a++)
        #pragma unroll
        for (int b = 0; b < 4; b++)
            #pragma unroll
            for (int c = 0; c < 4; c++) acc[a][b][c] = 0.f;

    int lrow = tid >> 3, lchunk = tid & 7;    // 32 rows x 8 chunks of 8 halves
    const __half* Ag = A  + (size_t)(bm + lrow) * NHID + lchunk * 8;
    const __half* Bg = Bw + (size_t)(bn + lrow) * NHID + lchunk * 8;
    __half* Asp = &As[lrow * LDS + lchunk * 8];
    __half* Bsp = &Bs[lrow * LDS + lchunk * 8];

    for (int k0 = 0; k0 < NHID; k0 += 64) {
        #pragma unroll
        for (int r = 0; r < 4; r++) {
            *(float4*)(Asp + r * 32 * LDS) = *(const float4*)(Ag + (size_t)r * 32 * NHID + k0);
            *(float4*)(Bsp + r * 32 * LDS) = *(const float4*)(Bg + (size_t)r * 32 * NHID + k0);
        }
        __syncthreads();
        #pragma unroll
        for (int kk = 0; kk < 4; kk++) {
            uint32_t af[4][4], bf[2][4];
            #pragma unroll
            for (int mi = 0; mi < 4; mi++) {
                uint32_t addr = smem_u32(&As[(wm*64 + mi*16 + (lane & 15)) * LDS
                                             + kk*16 + ((lane >> 4) << 3)]);
                asm volatile("ldmatrix.sync.aligned.m8n8.x4.shared.b16 {%0,%1,%2,%3}, [%4];"
                    : "=r"(af[mi][0]), "=r"(af[mi][1]), "=r"(af[mi][2]), "=r"(af[mi][3])
                    : "r"(addr));
            }
            #pragma unroll
            for (int nb = 0; nb < 2; nb++) {
                uint32_t addr = smem_u32(&Bs[(wn*32 + nb*16 + (lane & 7) + ((lane >> 4) << 3)) * LDS
                                             + kk*16 + (lane & 8)]);
                asm volatile("ldmatrix.sync.aligned.m8n8.x4.shared.b16 {%0,%1,%2,%3}, [%4];"
                    : "=r"(bf[nb][0]), "=r"(bf[nb][1]), "=r"(bf[nb][2]), "=r"(bf[nb][3])
                    : "r"(addr));
            }
            #pragma unroll
            for (int mi = 0; mi < 4; mi++)
                #pragma unroll
                for (int ni = 0; ni < 4; ni++) {
                    uint32_t b0 = bf[ni >> 1][(ni & 1) * 2];
                    uint32_t b1 = bf[ni >> 1][(ni & 1) * 2 + 1];
                    asm volatile(
                        "mma.sync.aligned.m16n8k16.row.col.f32.f16.f16.f32 "
                        "{%0,%1,%2,%3}, {%4,%5,%6,%7}, {%8,%9}, {%0,%1,%2,%3};"
                        : "+f"(acc[mi][ni][0]), "+f"(acc[mi][ni][1]),
                          "+f"(acc[mi][ni][2]), "+f"(acc[mi][ni][3])
                        : "r"(af[mi][0]), "r"(af[mi][1]), "r"(af[mi][2]), "r"(af[mi][3]),
                          "r"(b0), "r"(b1));
                }
        }
        __syncthreads();
    }

    // epilogue: (row, col) pairs per C-fragment; col pair = rope pair (even, odd)
    #pragma unroll
    for (int mi = 0; mi < 4; mi++) {
        int r0 = bm + wm*64 + mi*16 + (lane >> 2);
        #pragma unroll
        for (int ni = 0; ni < 4; ni++) {
            int cc = bn + wn*32 + ni*8 + ((lane & 3) << 1);
            float v0 = acc[mi][ni][0], v1 = acc[mi][ni][1];
            float v2 = acc[mi][ni][2], v3 = acc[mi][ni][3];
            if (WHICH) {
                int j = (cc >> 1) & 63;
                float2 cs0 = d_cs[(r0 & (NS-1)) * 64 + j];
                float2 cs1 = d_cs[((r0 + 8) & (NS-1)) * 64 + j];
                float t0 = v0*cs0.x - v1*cs0.y;
                float t1 = v1*cs0.x + v0*cs0.y;
                float t2 = v2*cs1.x - v3*cs1.y;
                float t3 = v3*cs1.x + v2*cs1.y;
                v0 = t0; v1 = t1; v2 = t2; v3 = t3;
            }
            *(__half2*)(C + (size_t)r0 * NHID + cc)       = __floats2half2_rn(v0, v1);
            *(__half2*)(C + (size_t)(r0 + 8) * NHID + cc) = __floats2half2_rn(v2, v3);
        }
    }
}

// ---------------- scores[b,h,s] = (R_s^T q_h) . K[b,s,h,:]  (warp per task) ----------------
__global__ void __launch_bounds__(256) scores_kernel(const float* __restrict__ q) {
    int task = blockIdx.x * 8 + (threadIdx.x >> 5);   // bs*32 + h
    int lane = threadIdx.x & 31;
    int bs = task >> 5, h = task & 31;
    int s  = bs & (NS - 1);
    const __half* kp = d_K16 + (size_t)bs * NHID + h * ND + lane * 4;
    __half2 ka = *(const __half2*)kp;
    __half2 kb = *(const __half2*)(kp + 2);
    float2 cs0 = d_cs[s * 64 + lane * 2];
    float2 cs1 = d_cs[s * 64 + lane * 2 + 1];
    const float* qp = q + h * ND + lane * 4;
    float q0 = __ldg(qp), q1 = __ldg(qp+1), q2 = __ldg(qp+2), q3 = __ldg(qp+3);
    float sum = (q0*cs0.x + q1*cs0.y) * __low2float(ka)
              + (q1*cs0.x - q0*cs0.y) * __high2float(ka)
              + (q2*cs1.x + q3*cs1.y) * __low2float(kb)
              + (q3*cs1.x - q2*cs1.y) * __high2float(kb);
    sum = warp_sum_all(sum);
    if (lane == 0) {
        int b = bs >> 11;
        d_scores[((b * NH + h) << 11) + s] = sum;
    }
}

// ---------------- softmax over s (block per (b,h)) ----------------
__global__ void __launch_bounds__(256) softmax_kernel() {
    int bh = blockIdx.x;
    const float* sc = d_scores + (size_t)bh * NS;
    float* at = d_attn + (size_t)bh * NS;
    float v[8]; float m = -1e30f;
    #pragma unroll
    for (int i = 0; i < 8; i++) { v[i] = sc[threadIdx.x + i*256]; m = fmaxf(m, v[i]); }
    m = warp_max_all(m);
    __shared__ float r[8];
    int wid = threadIdx.x >> 5;
    if ((threadIdx.x & 31) == 0) r[wid] = m;
    __syncthreads();
    if (threadIdx.x == 0) { float t = r[0]; for (int w = 1; w < 8; w++) t = fmaxf(t, r[w]); r[0] = t; }
    __syncthreads();
    m = r[0];
    float tot = 0.f;
    #pragma unroll
    for (int i = 0; i < 8; i++) { v[i] = expf(v[i] - m); tot += v[i]; }
    tot = warp_sum_all(tot);
    __syncthreads();
    if ((threadIdx.x & 31) == 0) r[wid] = tot;
    __syncthreads();
    if (threadIdx.x == 0) { float t = 0; for (int w = 0; w < 8; w++) t += r[w]; r[0] = t; }
    __syncthreads();
    float inv = 1.f / r[0];
    #pragma unroll
    for (int i = 0; i < 8; i++) at[threadIdx.x + i*256] = v[i] * inv;
}

// ---------------- attn @ V (split-K over s, then reduce) ----------------
__global__ void __launch_bounds__(128) attnv_kernel() {
    int bh = blockIdx.x, ch = blockIdx.y;
    int b = bh >> 5, h = bh & 31;
    const float* at = d_attn + (size_t)bh * NS + ch * 256;
    const __half* vp = d_V16 + (size_t)(b * NS + ch * 256) * NHID + h * ND + threadIdx.x;
    float acc = 0.f;
    #pragma unroll 8
    for (int i = 0; i < 256; i++)
        acc += at[i] * __half2float(vp[(size_t)i * NHID]);
    d_attnv_part[ch][bh * ND + threadIdx.x] = acc;
}
__global__ void __launch_bounds__(256) attnv_reduce() {
    int i = blockIdx.x * 256 + threadIdx.x;   // (b*32+h)*128+d == b*4096 + h*128 + d
    float s = 0.f;
    #pragma unroll
    for (int c = 0; c < 8; c++) s += d_attnv_part[c][i];
    d_attn_out[i] = s;
}

// ---------------- 4-row GEMV: y[b][i] = sum_k W[i,k] x[b,k] (+bias) ----------------
__device__ __forceinline__ void gemv4_body(const float* __restrict__ W, const float* __restrict__ x,
                                           float* __restrict__ y, const float* __restrict__ bias,
                                           int K, int N) {
    int i = blockIdx.x;
    const float* w = W + (size_t)i * K;
    float a0 = 0, a1 = 0, a2 = 0, a3 = 0;
    for (int k = threadIdx.x; k < K; k += 256) {
        float wv = __ldg(w + k);
        a0 += wv * __ldg(x + k);
        a1 += wv * __ldg(x + K + k);
        a2 += wv * __ldg(x + 2*K + k);
        a3 += wv * __ldg(x + 3*K + k);
    }
    a0 = warp_sum_all(a0); a1 = warp_sum_all(a1);
    a2 = warp_sum_all(a2); a3 = warp_sum_all(a3);
    __shared__ float red[8][4];
    int wid = threadIdx.x >> 5;
    if ((threadIdx.x & 31) == 0) { red[wid][0]=a0; red[wid][1]=a1; red[wid][2]=a2; red[wid][3]=a3; }
    __syncthreads();
    if (threadIdx.x < 4) {
        float s = 0.f;
        #pragma unroll
        for (int w8 = 0; w8 < 8; w8++) s += red[w8][threadIdx.x];
        if (bias) s += __ldg(bias + i);
        y[(size_t)threadIdx.x * N + i] = s;
    }
}
__global__ void __launch_bounds__(256) gemv_wo(const float* __restrict__ Wo) {
    gemv4_body(Wo, d_attn_out, d_y1, nullptr, NHID, NHID);
}
__global__ void __launch_bounds__(256) gemv_w2(const float* __restrict__ W2) {
    gemv4_body(W2, d_cbuf, d_y2, nullptr, MLPDIM, NHID);
}
__global__ void __launch_bounds__(256) gemv_ws(const float* __restrict__ Ws,
                                               const float* __restrict__ bias,
                                               float* __restrict__ out) {
    gemv4_body(Ws, d_ln2, out, bias, NHID, 2048);
}

// ---------------- fused W0/W1 + SiLU-gate ----------------
__global__ void __launch_bounds__(256) mlp_kernel(const float* __restrict__ W0,
                                                  const float* __restrict__ W1) {
    int i = blockIdx.x;
    const float* w0 = W0 + (size_t)i * NHID;
    const float* w1 = W1 + (size_t)i * NHID;
    float a[4] = {0,0,0,0}, g[4] = {0,0,0,0};
    for (int k = threadIdx.x; k < NHID; k += 256) {
        float v0 = __ldg(w0 + k), v1 = __ldg(w1 + k);
        #pragma unroll
        for (int b = 0; b < 4; b++) {
            float xv = __ldg(d_ln1 + (size_t)b * NHID + k);
            a[b] += v0 * xv; g[b] += v1 * xv;
        }
    }
    __shared__ float ra[8][4], rg[8][4];
    int wid = threadIdx.x >> 5;
    #pragma unroll
    for (int b = 0; b < 4; b++) { a[b] = warp_sum_all(a[b]); g[b] = warp_sum_all(g[b]); }
    if ((threadIdx.x & 31) == 0) {
        #pragma unroll
        for (int b = 0; b < 4; b++) { ra[wid][b] = a[b]; rg[wid][b] = g[b]; }
    }
    __syncthreads();
    if (threadIdx.x < 4) {
        float sa = 0.f, sg = 0.f;
        #pragma unroll
        for (int w = 0; w < 8; w++) { sa += ra[w][threadIdx.x]; sg += rg[w][threadIdx.x]; }
        float si = sg / (1.f + expf(-sg));
        d_cbuf[(size_t)threadIdx.x * MLPDIM + i] = sa * si;
    }
}

// ---------------- layernorm (block per batch row) ----------------
template<int STAGE>
__global__ void __launch_bounds__(256) ln_kernel(const float* __restrict__ g,
                                                 const float* __restrict__ bb) {
    const float* x = (STAGE == 0 ? d_y1 : d_y2) + (size_t)blockIdx.x * NHID;
    float* y       = (STAGE == 0 ? d_ln1 : d_ln2) + (size_t)blockIdx.x * NHID;
    float s = 0.f, s2 = 0.f;
    for (int k = threadIdx.x; k < NHID; k += 256) { float v = x[k]; s += v; s2 += v*v; }
    s = warp_sum_all(s); s2 = warp_sum_all(s2);
    __shared__ float rs[8], rs2[8];
    int wid = threadIdx.x >> 5;
    if ((threadIdx.x & 31) == 0) { rs[wid] = s; rs2[wid] = s2; }
    __syncthreads();
    if (threadIdx.x == 0) {
        float t = 0, t2 = 0;
        for (int w = 0; w < 8; w++) { t += rs[w]; t2 += rs2[w]; }
        rs[0] = t; rs2[0] = t2;
    }
    __syncthreads();
    float mu  = rs[0] / (float)NHID;
    float var = rs2[0] / (float)NHID - mu * mu;
    float inv = rsqrtf(var + 1e-5f);
    for (int k = threadIdx.x; k < NHID; k += 256)
        y[k] = (x[k] - mu) * inv * __ldg(g + k) + __ldg(bb + k);
}

// ---------------- launch ----------------
extern "C" void kernel_launch(void* const* d_in, const int* in_sizes, int n_in,
                              void* d_out, int out_size) {
    const float* hidden = (const float*)d_in[0];
    const float* q      = (const float*)d_in[1];
    const float* Wk     = (const float*)d_in[2];
    const float* Wv     = (const float*)d_in[3];
    const float* Wo     = (const float*)d_in[4];
    const float* W0     = (const float*)d_in[5];
    const float* W1     = (const float*)d_in[6];
    const float* W2     = (const float*)d_in[7];
    const float* Ws     = (const float*)d_in[8];
    const float* bs     = (const float*)d_in[9];
    const float* ln_g   = (const float*)d_in[10];
    const float* ln_b   = (const float*)d_in[11];
    float* out = (float*)d_out;

    cvt_all<<<65536, 256>>>(hidden, Wk, Wv);
    cs_kernel<<<512, 256>>>();
    gemm_kernel<0><<<dim3(32, 64), 256>>>();   // K = X Wk^T
    gemm_kernel<1><<<dim3(32, 64), 256>>>();   // V = rope(X Wv^T)
    scores_kernel<<<32768, 256>>>(q);
    softmax_kernel<<<128, 256>>>();
    attnv_kernel<<<dim3(128, 8), 128>>>();
    attnv_reduce<<<64, 256>>>();
    gemv_wo<<<4096, 256>>>(Wo);
    ln_kernel<0><<<4, 256>>>(ln_g, ln_b);
    mlp_kernel<<<12288, 256>>>(W0, W1);
    gemv_w2<<<4096, 256>>>(W2);
    ln_kernel<1><<<4, 256>>>(ln_g, ln_b);
    gemv_ws<<<2048, 256>>>(Ws, bs, out);
}